// round 6
// baseline (speedup 1.0000x reference)
#include <cuda_runtime.h>
#include <cuda_bf16.h>
#include <math.h>
#include <stdint.h>

#define TT 512
#define DD 512
#define LOG2E 1.4426950408889634f

// GEMM smem geometry
#define ROWB 144                 // 64 bf16 + 8 pad = 144 bytes per row
#define MAT  (64 * ROWB)         // one 64x64 bf16 matrix = 9216 B
#define BUF  (4 * MAT)           // Ahi, Alo, Bhi, Blo
#define GEMM_SMEM (2 * BUF)      // double buffered = 73728 B

// ---------------------------------------------------------------------------
// Device-global scratch
// ---------------------------------------------------------------------------
__device__ float g_qkv[3 * DD * TT];                     // [w][o][t] fp32
__device__ __align__(16) __nv_bfloat16 g_aohi[DD * TT];  // ao hi, [d][t]
__device__ __align__(16) __nv_bfloat16 g_aolo[DD * TT];  // ao lo residual

__device__ __forceinline__ uint32_t smem_u32(const void* p) {
    uint32_t a;
    asm("{ .reg .u64 t; cvta.to.shared.u64 t, %1; cvt.u32.u64 %0, t; }"
        : "=r"(a) : "l"(p));
    return a;
}
__device__ __forceinline__ void cp16(uint32_t dst, const void* src) {
    asm volatile("cp.async.ca.shared.global [%0], [%1], 16;"
                 :: "r"(dst), "l"(src) : "memory");
}
__device__ __forceinline__ float fast_ex2(float x) {
    float r;
    asm("ex2.approx.ftz.f32 %0, %1;" : "=f"(r) : "f"(x));
    return r;
}

#define MMA16816(c, a, b) \
    asm volatile( \
        "mma.sync.aligned.m16n8k16.row.col.f32.bf16.bf16.f32 " \
        "{%0,%1,%2,%3},{%4,%5,%6,%7},{%8,%9},{%0,%1,%2,%3};" \
        : "+f"((c)[0]), "+f"((c)[1]), "+f"((c)[2]), "+f"((c)[3]) \
        : "r"((a)[0]), "r"((a)[1]), "r"((a)[2]), "r"((a)[3]), \
          "r"((b)[0]), "r"((b)[1]))

#define LDMX4T(r, a) \
    asm volatile( \
        "ldmatrix.sync.aligned.m8n8.x4.trans.shared.b16 {%0,%1,%2,%3}, [%4];" \
        : "=r"((r)[0]), "=r"((r)[1]), "=r"((r)[2]), "=r"((r)[3]) : "r"(a))

// fp32x4 -> packed bf16 hi (uint2) + bf16 lo residual (uint2)
__device__ __forceinline__ void cvt_f4(const float4 v, uint2& hi, uint2& lo) {
    __nv_bfloat162 h0 = __float22bfloat162_rn(make_float2(v.x, v.y));
    __nv_bfloat162 h1 = __float22bfloat162_rn(make_float2(v.z, v.w));
    float2 r0 = make_float2(v.x - __bfloat162float(h0.x),
                            v.y - __bfloat162float(h0.y));
    float2 r1 = make_float2(v.z - __bfloat162float(h1.x),
                            v.w - __bfloat162float(h1.y));
    __nv_bfloat162 l0 = __float22bfloat162_rn(r0);
    __nv_bfloat162 l1 = __float22bfloat162_rn(r1);
    hi.x = *(unsigned*)&h0; hi.y = *(unsigned*)&h1;
    lo.x = *(unsigned*)&l0; lo.y = *(unsigned*)&l1;
}

// ---------------------------------------------------------------------------
// GEMM1: C[m][n] = sum_k W[m%512][k] * x[n][k]  (m = qkv row 0..1536, n = t)
// fp32 inputs converted to bf16 hi/lo in-kernel. 64x64 tiles, 128 threads.
// ---------------------------------------------------------------------------
__global__ void __launch_bounds__(128) gemm1_kernel(
        const float4* __restrict__ x,  const float4* __restrict__ Wq,
        const float4* __restrict__ Wk, const float4* __restrict__ Wv) {
    extern __shared__ char smem[];
    const int tid = threadIdx.x, wid = tid >> 5, lane = tid & 31;
    const int g = lane >> 2, t4 = lane & 3;
    const int wm = (wid >> 1) * 32, wn = (wid & 1) * 32;
    const int m0 = blockIdx.x * 64, n0 = blockIdx.y * 64;
    const float4* W = (m0 < 512) ? Wq : (m0 < 1024 ? Wk : Wv);
    const int mb = m0 & 511;
    const int lrow = tid >> 1;          // 0..63
    const int lf0 = (tid & 1) * 8;      // f4 col base (0 or 8)

    float4 ra[8], rb[8];
    float acc[2][4][4] = {};

#pragma unroll
    for (int i = 0; i < 8; i++) {
        ra[i] = W[(size_t)(mb + lrow) * 128 + lf0 + i];
        rb[i] = x[(size_t)(n0 + lrow) * 128 + lf0 + i];
    }

    for (int c = 0; c < 8; c++) {
        __syncthreads();
        char* sb = smem + (c & 1) * BUF;
        const int off = lrow * ROWB + lf0 * 8;
#pragma unroll
        for (int i = 0; i < 8; i++) {
            uint2 h, l;
            cvt_f4(ra[i], h, l);
            *(uint2*)(sb + off + i * 8) = h;
            *(uint2*)(sb + MAT + off + i * 8) = l;
            cvt_f4(rb[i], h, l);
            *(uint2*)(sb + 2 * MAT + off + i * 8) = h;
            *(uint2*)(sb + 3 * MAT + off + i * 8) = l;
        }
        __syncthreads();

        if (c < 7) {
#pragma unroll
            for (int i = 0; i < 8; i++) {
                ra[i] = W[(size_t)(mb + lrow) * 128 + (c + 1) * 16 + lf0 + i];
                rb[i] = x[(size_t)(n0 + lrow) * 128 + (c + 1) * 16 + lf0 + i];
            }
        }

        const char* sAh = sb;
        const char* sAl = sb + MAT;
        const char* sBh = sb + 2 * MAT;
        const char* sBl = sb + 3 * MAT;
#pragma unroll
        for (int ks = 0; ks < 4; ks++) {
            const int kO = ks * 32;
            uint32_t ah[2][4], al[2][4], bh[4][2], bl[4][2];
#pragma unroll
            for (int mt = 0; mt < 2; mt++) {
                const int r = wm + mt * 16 + g;
                const char* p0 = sAh + r * ROWB + kO + 4 * t4;
                const char* p1 = sAl + r * ROWB + kO + 4 * t4;
                ah[mt][0] = *(const uint32_t*)(p0);
                ah[mt][1] = *(const uint32_t*)(p0 + 8 * ROWB);
                ah[mt][2] = *(const uint32_t*)(p0 + 16);
                ah[mt][3] = *(const uint32_t*)(p0 + 8 * ROWB + 16);
                al[mt][0] = *(const uint32_t*)(p1);
                al[mt][1] = *(const uint32_t*)(p1 + 8 * ROWB);
                al[mt][2] = *(const uint32_t*)(p1 + 16);
                al[mt][3] = *(const uint32_t*)(p1 + 8 * ROWB + 16);
            }
#pragma unroll
            for (int nt = 0; nt < 4; nt++) {
                const int r = wn + nt * 8 + g;
                const char* p0 = sBh + r * ROWB + kO + 4 * t4;
                const char* p1 = sBl + r * ROWB + kO + 4 * t4;
                bh[nt][0] = *(const uint32_t*)(p0);
                bh[nt][1] = *(const uint32_t*)(p0 + 16);
                bl[nt][0] = *(const uint32_t*)(p1);
                bl[nt][1] = *(const uint32_t*)(p1 + 16);
            }
#pragma unroll
            for (int mt = 0; mt < 2; mt++)
#pragma unroll
                for (int nt = 0; nt < 4; nt++) {
                    MMA16816(acc[mt][nt], ah[mt], bh[nt]);
                    MMA16816(acc[mt][nt], ah[mt], bl[nt]);
                    MMA16816(acc[mt][nt], al[mt], bh[nt]);
                }
        }
    }

#pragma unroll
    for (int mt = 0; mt < 2; mt++) {
        const int r = m0 + wm + mt * 16 + g;
#pragma unroll
        for (int nt = 0; nt < 4; nt++) {
            const int col = n0 + wn + nt * 8 + 2 * t4;
            *(float2*)&g_qkv[(size_t)r * 512 + col] =
                make_float2(acc[mt][nt][0], acc[mt][nt][1]);
            *(float2*)&g_qkv[(size_t)(r + 8) * 512 + col] =
                make_float2(acc[mt][nt][2], acc[mt][nt][3]);
        }
    }
}

// ---------------------------------------------------------------------------
// Attention with fused RoPE; writes bf16 hi/lo split directly ([d][t]).
// ---------------------------------------------------------------------------
__global__ void __launch_bounds__(256) attn_kernel() {
    const int c  = blockIdx.x;
    const int h  = c >> 6;
    const int ch = c & 63;
    const int fi = ch & 31;
    const int pc = ((h < 4) ? (h + 4) : (h - 4)) * 64 + ch;
    const float sgn = (h < 4) ? -1.0f : 1.0f;

    const float* q  = g_qkv + 0 * DD * TT + c  * TT;
    const float* qp = g_qkv + 0 * DD * TT + pc * TT;
    const float* k  = g_qkv + 1 * DD * TT + c  * TT;
    const float* kp = g_qkv + 1 * DD * TT + pc * TT;
    const float* v  = g_qkv + 2 * DD * TT + c  * TT;

    __shared__ float ks[512];
    __shared__ float vs[512];
    __shared__ float cs[512];
    __shared__ float sn[512];
    __shared__ float s_invf;

    const int tid = threadIdx.x;
    if (tid == 0) s_invf = (float)pow(10000.0, -(double)(2 * fi) / 64.0);
    __syncthreads();
    const float invf = s_invf;

#pragma unroll
    for (int off = 0; off < 512; off += 256) {
        const int tt = tid + off;
        float sv, cv;
        sincosf((float)tt * invf, &sv, &cv);
        cs[tt] = cv;
        sn[tt] = sv;
        ks[tt] = k[tt] * cv + sgn * kp[tt] * sv;
        vs[tt] = v[tt];
    }
    __syncthreads();

#pragma unroll
    for (int rep = 0; rep < 2; rep++) {
        const int i = rep ? (511 - tid) : tid;
        const float qr = q[i] * cs[i] + sgn * qp[i] * sn[i];
        const float qs = qr * (0.125f * LOG2E);
        float l = 0.f, acc = 0.f;
#pragma unroll 4
        for (int j = 0; j <= i; j++) {
            float p = fast_ex2(qs * ks[j]);
            l += p;
            acc += p * vs[j];
        }
        const float o = acc / l;
        const __nv_bfloat16 hb = __float2bfloat16(o);
        g_aohi[c * TT + i] = hb;
        g_aolo[c * TT + i] = __float2bfloat16(o - __bfloat162float(hb));
    }
}

// ---------------------------------------------------------------------------
// GEMM2: y[m][n] = sum_k ao[k][m] * Wo[n][k]  (m = t, n = o, k = d)
// A (ao) is bf16 hi/lo in [k][m] layout -> cp.async + ldmatrix.trans.
// B (Wo) fp32 -> converted in-kernel. 64x64 tiles, 128 threads.
// ---------------------------------------------------------------------------
__global__ void __launch_bounds__(128) gemm2_kernel(
        const float4* __restrict__ Wo, float* __restrict__ y) {
    extern __shared__ char smem[];
    const uint32_t s0 = smem_u32(smem);
    const int tid = threadIdx.x, wid = tid >> 5, lane = tid & 31;
    const int g = lane >> 2, t4 = lane & 3;
    const int wm = (wid >> 1) * 32, wn = (wid & 1) * 32;
    const int m0 = blockIdx.x * 64;   // t
    const int n0 = blockIdx.y * 64;   // o

    // ldmatrix lane addressing
    const int laneRow  = ((lane >> 4) & 1) * 8 + (lane & 7);
    const int laneMsel = ((lane >> 3) & 1) * 8;

    // A cp.async mapping: 64 k-rows x 8 chunks of 16B, hi + lo
    const int ar  = tid >> 1;          // 0..63 (k row)
    const int ac0 = (tid & 1) * 4;     // 16B-chunk base (0 or 4)
    const uint4* AH = (const uint4*)g_aohi;
    const uint4* AL = (const uint4*)g_aolo;

    // B loader mapping (fp32 convert)
    const int lrow = tid >> 1;
    const int lf0 = (tid & 1) * 8;

    float4 rb[8];
    float acc[2][4][4] = {};

    auto cpA = [&](int c, int b) {
        const uint32_t base = s0 + b * BUF;
#pragma unroll
        for (int i = 0; i < 4; i++) {
            const int c16 = ac0 + i;
            const uint32_t so = ar * ROWB + c16 * 16;
            const size_t gi = (size_t)(c * 64 + ar) * 64 + (m0 >> 3) + c16;
            cp16(base + so,       AH + gi);
            cp16(base + MAT + so, AL + gi);
        }
        asm volatile("cp.async.commit_group;" ::: "memory");
    };

#pragma unroll
    for (int i = 0; i < 8; i++)
        rb[i] = Wo[(size_t)(n0 + lrow) * 128 + lf0 + i];
    cpA(0, 0);

    for (int c = 0; c < 8; c++) {
        __syncthreads();
        char* sb = smem + (c & 1) * BUF;
        const int off = lrow * ROWB + lf0 * 8;
#pragma unroll
        for (int i = 0; i < 8; i++) {
            uint2 h, l;
            cvt_f4(rb[i], h, l);
            *(uint2*)(sb + 2 * MAT + off + i * 8) = h;
            *(uint2*)(sb + 3 * MAT + off + i * 8) = l;
        }
        if (c < 7) {
            cpA(c + 1, (c + 1) & 1);
#pragma unroll
            for (int i = 0; i < 8; i++)
                rb[i] = Wo[(size_t)(n0 + lrow) * 128 + (c + 1) * 16 + lf0 + i];
            asm volatile("cp.async.wait_group 1;" ::: "memory");
        } else {
            asm volatile("cp.async.wait_group 0;" ::: "memory");
        }
        __syncthreads();

        const uint32_t sA_u = s0 + (c & 1) * BUF;
        const char* sBh = sb + 2 * MAT;
        const char* sBl = sb + 3 * MAT;
#pragma unroll
        for (int ks = 0; ks < 4; ks++) {
            const int kO = ks * 32;
            uint32_t ah[2][4], al[2][4], bh[4][2], bl[4][2];
#pragma unroll
            for (int mt = 0; mt < 2; mt++) {
                const uint32_t ad = sA_u + (ks * 16 + laneRow) * ROWB
                                  + (wm + mt * 16 + laneMsel) * 2;
                LDMX4T(ah[mt], ad);
                LDMX4T(al[mt], ad + MAT);
            }
#pragma unroll
            for (int nt = 0; nt < 4; nt++) {
                const int r = wn + nt * 8 + g;
                const char* p0 = sBh + r * ROWB + kO + 4 * t4;
                const char* p1 = sBl + r * ROWB + kO + 4 * t4;
                bh[nt][0] = *(const uint32_t*)(p0);
                bh[nt][1] = *(const uint32_t*)(p0 + 16);
                bl[nt][0] = *(const uint32_t*)(p1);
                bl[nt][1] = *(const uint32_t*)(p1 + 16);
            }
#pragma unroll
            for (int mt = 0; mt < 2; mt++)
#pragma unroll
                for (int nt = 0; nt < 4; nt++) {
                    MMA16816(acc[mt][nt], ah[mt], bh[nt]);
                    MMA16816(acc[mt][nt], ah[mt], bl[nt]);
                    MMA16816(acc[mt][nt], al[mt], bh[nt]);
                }
        }
    }

#pragma unroll
    for (int mt = 0; mt < 2; mt++) {
        const int r = m0 + wm + mt * 16 + g;     // t row
#pragma unroll
        for (int nt = 0; nt < 4; nt++) {
            const int col = n0 + wn + nt * 8 + 2 * t4;
            *(float2*)&y[(size_t)r * 512 + col] =
                make_float2(acc[mt][nt][0], acc[mt][nt][1]);
            *(float2*)&y[(size_t)(r + 8) * 512 + col] =
                make_float2(acc[mt][nt][2], acc[mt][nt][3]);
        }
    }
}

// ---------------------------------------------------------------------------
extern "C" void kernel_launch(void* const* d_in, const int* in_sizes, int n_in,
                              void* d_out, int out_size) {
    const float* x  = (const float*)d_in[0];
    const float* Wq = (const float*)d_in[1];
    const float* Wk = (const float*)d_in[2];
    const float* Wv = (const float*)d_in[3];
    const float* Wo = (const float*)d_in[4];
    float* y = (float*)d_out;

    cudaFuncSetAttribute(gemm1_kernel,
                         cudaFuncAttributeMaxDynamicSharedMemorySize, GEMM_SMEM);
    cudaFuncSetAttribute(gemm2_kernel,
                         cudaFuncAttributeMaxDynamicSharedMemorySize, GEMM_SMEM);

    gemm1_kernel<<<dim3(24, 8), 128, GEMM_SMEM>>>(
        (const float4*)x, (const float4*)Wq,
        (const float4*)Wk, (const float4*)Wv);
    attn_kernel<<<512, 256>>>();
    gemm2_kernel<<<dim3(8, 8), 128, GEMM_SMEM>>>((const float4*)Wo, y);
}

// round 7
// speedup vs baseline: 1.4765x; 1.4765x over previous
#include <cuda_runtime.h>
#include <cuda_bf16.h>
#include <math.h>
#include <stdint.h>

#define TT 512
#define DD 512
#define LOG2E 1.4426950408889634f

// GEMM smem geometry
#define ROWB 144                 // 64 bf16 + 8 pad = 144 bytes per row
#define MAT  (64 * ROWB)         // one 64x64 bf16 matrix = 9216 B
#define BUF  (4 * MAT)           // Ahi, Alo, Bhi, Blo
#define GEMM_SMEM (2 * BUF)      // double buffered = 73728 B

// ---------------------------------------------------------------------------
// Device-global scratch
// ---------------------------------------------------------------------------
__device__ float g_qkv[3 * DD * TT];                     // [w][o][t] fp32
__device__ __align__(16) __nv_bfloat16 g_aohi[DD * TT];  // ao hi, [d][t]
__device__ __align__(16) __nv_bfloat16 g_aolo[DD * TT];  // ao lo residual
__device__ __align__(16) __nv_bfloat16 gAhi[1536 * 512]; // Wq,Wk,Wv stacked hi
__device__ __align__(16) __nv_bfloat16 gAlo[1536 * 512];
__device__ __align__(16) __nv_bfloat16 gBhi[512 * 512];  // x [t][k]
__device__ __align__(16) __nv_bfloat16 gBlo[512 * 512];
__device__ __align__(16) __nv_bfloat16 gWohi[512 * 512]; // Wo [o][d]
__device__ __align__(16) __nv_bfloat16 gWolo[512 * 512];

__device__ __forceinline__ uint32_t smem_u32(const void* p) {
    uint32_t a;
    asm("{ .reg .u64 t; cvta.to.shared.u64 t, %1; cvt.u32.u64 %0, t; }"
        : "=r"(a) : "l"(p));
    return a;
}
__device__ __forceinline__ void cp16(uint32_t dst, const void* src) {
    asm volatile("cp.async.ca.shared.global [%0], [%1], 16;"
                 :: "r"(dst), "l"(src) : "memory");
}
__device__ __forceinline__ float fast_ex2(float x) {
    float r;
    asm("ex2.approx.ftz.f32 %0, %1;" : "=f"(r) : "f"(x));
    return r;
}

#define MMA16816(c, a, b) \
    asm volatile( \
        "mma.sync.aligned.m16n8k16.row.col.f32.bf16.bf16.f32 " \
        "{%0,%1,%2,%3},{%4,%5,%6,%7},{%8,%9},{%0,%1,%2,%3};" \
        : "+f"((c)[0]), "+f"((c)[1]), "+f"((c)[2]), "+f"((c)[3]) \
        : "r"((a)[0]), "r"((a)[1]), "r"((a)[2]), "r"((a)[3]), \
          "r"((b)[0]), "r"((b)[1]))

#define LDMX4(r, a) \
    asm volatile( \
        "ldmatrix.sync.aligned.m8n8.x4.shared.b16 {%0,%1,%2,%3}, [%4];" \
        : "=r"((r)[0]), "=r"((r)[1]), "=r"((r)[2]), "=r"((r)[3]) : "r"(a))

#define LDMX4T(r, a) \
    asm volatile( \
        "ldmatrix.sync.aligned.m8n8.x4.trans.shared.b16 {%0,%1,%2,%3}, [%4];" \
        : "=r"((r)[0]), "=r"((r)[1]), "=r"((r)[2]), "=r"((r)[3]) : "r"(a))

// ---------------------------------------------------------------------------
// Split kernel: fp32 -> bf16 hi + bf16 lo(residual).  (verified round 5)
// Segments (each 65536 float4s): 0=Wq 1=Wk 2=Wv -> gA*; 3=x -> gB*; 4=Wo.
// ---------------------------------------------------------------------------
__global__ void __launch_bounds__(256) split_kernel(
        const float4* __restrict__ x,  const float4* __restrict__ Wq,
        const float4* __restrict__ Wk, const float4* __restrict__ Wv,
        const float4* __restrict__ Wo) {
    const int gid = blockIdx.x * 256 + threadIdx.x;   // 0..327679
    const int seg = gid >> 16;
    const int off = gid & 65535;

    const float4* src;
    __nv_bfloat16 *dh, *dl;
    switch (seg) {
        case 0: src = Wq; dh = gAhi;          dl = gAlo;          break;
        case 1: src = Wk; dh = gAhi + 262144; dl = gAlo + 262144; break;
        case 2: src = Wv; dh = gAhi + 524288; dl = gAlo + 524288; break;
        case 3: src = x;  dh = gBhi;          dl = gBlo;          break;
        default: src = Wo; dh = gWohi;         dl = gWolo;         break;
    }
    float4 v = src[off];
    __nv_bfloat16 h0 = __float2bfloat16(v.x), h1 = __float2bfloat16(v.y);
    __nv_bfloat16 h2 = __float2bfloat16(v.z), h3 = __float2bfloat16(v.w);
    __nv_bfloat16 l0 = __float2bfloat16(v.x - __bfloat162float(h0));
    __nv_bfloat16 l1 = __float2bfloat16(v.y - __bfloat162float(h1));
    __nv_bfloat16 l2 = __float2bfloat16(v.z - __bfloat162float(h2));
    __nv_bfloat16 l3 = __float2bfloat16(v.w - __bfloat162float(h3));
    __nv_bfloat162* oh = (__nv_bfloat162*)dh;
    __nv_bfloat162* ol = (__nv_bfloat162*)dl;
    __nv_bfloat162 a, b;
    a.x = h0; a.y = h1; b.x = h2; b.y = h3;
    oh[off * 2] = a; oh[off * 2 + 1] = b;
    a.x = l0; a.y = l1; b.x = l2; b.y = l3;
    ol[off * 2] = a; ol[off * 2 + 1] = b;
}

// ---------------------------------------------------------------------------
// GEMM core: C[(m0+r)*512 + n0+c] = sum_k A[r][k]*B[c][k]
//   ATRANS=false: A bf16 [m][k] row-major (hi/lo), ldmatrix non-trans
//   ATRANS=true : A bf16 [k][m]            (hi/lo), ldmatrix trans
// 64x64 CTA tile, 256 threads (8 warps, warp tile 32x16),
// cp.async double-buffered, 3-pass hi/lo MMA.
// ---------------------------------------------------------------------------
template <bool ATRANS>
__device__ __forceinline__ void gemm_core(
        const uint4* __restrict__ AH, const uint4* __restrict__ AL,
        const uint4* __restrict__ BH, const uint4* __restrict__ BL,
        float* __restrict__ C) {
    extern __shared__ char smem[];
    const uint32_t s0 = smem_u32(smem);

    const int tid = threadIdx.x;       // 0..255
    const int wid = tid >> 5, lane = tid & 31;
    const int g = lane >> 2, t4 = lane & 3;
    const int wm = (wid >> 2) * 32;    // 2 m-groups
    const int wn = (wid & 3) * 16;     // 4 n-groups
    const int m0 = blockIdx.x * 64, n0 = blockIdx.y * 64;

    // ldmatrix lane addressing (derived from verified scalar fragment maps)
    const int arow  = lane & 15;               // non-trans A/B row sel
    const int aksel = (lane >> 4) * 16;        // k-half byte offset
    const int brow  = ((lane >> 4) & 1) * 8 + (lane & 7);
    const int bksel = ((lane >> 3) & 1) * 16;
    // trans-A lane addressing (verified round 6)
    const int laneRow  = ((lane >> 4) & 1) * 8 + (lane & 7);
    const int laneMsel = ((lane >> 3) & 1) * 8;

    float acc[2][2][4] = {};

    auto load_chunk = [&](int c, int b) {
        const uint32_t base = s0 + b * BUF;
#pragma unroll
        for (int it = 0; it < 2; it++) {
            const int idx = it * 256 + tid;     // 0..511
            const int row = idx >> 3, c16 = idx & 7;
            const uint32_t so = row * ROWB + c16 * 16;
            size_t ga;
            if (ATRANS) ga = (size_t)(c * 64 + row) * 64 + (m0 >> 3) + c16;
            else        ga = (size_t)(m0 + row) * 64 + c * 8 + c16;
            const size_t gb = (size_t)(n0 + row) * 64 + c * 8 + c16;
            cp16(base + so,           AH + ga);
            cp16(base + MAT + so,     AL + ga);
            cp16(base + 2 * MAT + so, BH + gb);
            cp16(base + 3 * MAT + so, BL + gb);
        }
        asm volatile("cp.async.commit_group;" ::: "memory");
    };

    load_chunk(0, 0);

    for (int c = 0; c < 8; c++) {
        if (c < 7) {
            load_chunk(c + 1, (c + 1) & 1);
            asm volatile("cp.async.wait_group 1;" ::: "memory");
        } else {
            asm volatile("cp.async.wait_group 0;" ::: "memory");
        }
        __syncthreads();

        const uint32_t sb = s0 + (c & 1) * BUF;
#pragma unroll
        for (int ks = 0; ks < 4; ks++) {
            const int kO = ks * 32;
            uint32_t ah[2][4], al[2][4], bh[4], bl[4];
#pragma unroll
            for (int mt = 0; mt < 2; mt++) {
                if (ATRANS) {
                    const uint32_t ad = sb + (ks * 16 + laneRow) * ROWB
                                      + (wm + mt * 16 + laneMsel) * 2;
                    LDMX4T(ah[mt], ad);
                    LDMX4T(al[mt], ad + MAT);
                } else {
                    const uint32_t ad = sb + (wm + mt * 16 + arow) * ROWB
                                      + kO + aksel;
                    LDMX4(ah[mt], ad);
                    LDMX4(al[mt], ad + MAT);
                }
            }
            {
                const uint32_t bd = sb + 2 * MAT + (wn + brow) * ROWB
                                  + kO + bksel;
                LDMX4(bh, bd);
                LDMX4(bl, bd + MAT);
            }
#pragma unroll
            for (int mt = 0; mt < 2; mt++)
#pragma unroll
                for (int nb = 0; nb < 2; nb++) {
                    MMA16816(acc[mt][nb], ah[mt], &bh[nb * 2]);
                    MMA16816(acc[mt][nb], ah[mt], &bl[nb * 2]);
                    MMA16816(acc[mt][nb], al[mt], &bh[nb * 2]);
                }
        }
        __syncthreads();
    }

#pragma unroll
    for (int mt = 0; mt < 2; mt++) {
        const int r = m0 + wm + mt * 16 + g;
#pragma unroll
        for (int nb = 0; nb < 2; nb++) {
            const int col = n0 + wn + nb * 8 + 2 * t4;
            *(float2*)&C[(size_t)r * 512 + col] =
                make_float2(acc[mt][nb][0], acc[mt][nb][1]);
            *(float2*)&C[(size_t)(r + 8) * 512 + col] =
                make_float2(acc[mt][nb][2], acc[mt][nb][3]);
        }
    }
}

__global__ void __launch_bounds__(256) gemm1_kernel() {
    gemm_core<false>((const uint4*)gAhi, (const uint4*)gAlo,
                     (const uint4*)gBhi, (const uint4*)gBlo, g_qkv);
}
__global__ void __launch_bounds__(256) gemm2_kernel(float* __restrict__ y) {
    gemm_core<true>((const uint4*)g_aohi, (const uint4*)g_aolo,
                    (const uint4*)gWohi, (const uint4*)gWolo, y);
}

// ---------------------------------------------------------------------------
// Attention with fused RoPE; writes bf16 hi/lo split directly ([d][t]).
// ---------------------------------------------------------------------------
__global__ void __launch_bounds__(256) attn_kernel() {
    const int c  = blockIdx.x;
    const int h  = c >> 6;
    const int ch = c & 63;
    const int fi = ch & 31;
    const int pc = ((h < 4) ? (h + 4) : (h - 4)) * 64 + ch;
    const float sgn = (h < 4) ? -1.0f : 1.0f;

    const float* q  = g_qkv + 0 * DD * TT + c  * TT;
    const float* qp = g_qkv + 0 * DD * TT + pc * TT;
    const float* k  = g_qkv + 1 * DD * TT + c  * TT;
    const float* kp = g_qkv + 1 * DD * TT + pc * TT;
    const float* v  = g_qkv + 2 * DD * TT + c  * TT;

    __shared__ float ks[512];
    __shared__ float vs[512];
    __shared__ float cs[512];
    __shared__ float sn[512];
    __shared__ float s_invf;

    const int tid = threadIdx.x;
    if (tid == 0) s_invf = (float)pow(10000.0, -(double)(2 * fi) / 64.0);
    __syncthreads();
    const float invf = s_invf;

#pragma unroll
    for (int off = 0; off < 512; off += 256) {
        const int tt = tid + off;
        float sv, cv;
        sincosf((float)tt * invf, &sv, &cv);
        cs[tt] = cv;
        sn[tt] = sv;
        ks[tt] = k[tt] * cv + sgn * kp[tt] * sv;
        vs[tt] = v[tt];
    }
    __syncthreads();

#pragma unroll
    for (int rep = 0; rep < 2; rep++) {
        const int i = rep ? (511 - tid) : tid;
        const float qr = q[i] * cs[i] + sgn * qp[i] * sn[i];
        const float qs = qr * (0.125f * LOG2E);
        float l = 0.f, acc = 0.f;
#pragma unroll 4
        for (int j = 0; j <= i; j++) {
            float p = fast_ex2(qs * ks[j]);
            l += p;
            acc += p * vs[j];
        }
        const float o = acc / l;
        const __nv_bfloat16 hb = __float2bfloat16(o);
        g_aohi[c * TT + i] = hb;
        g_aolo[c * TT + i] = __float2bfloat16(o - __bfloat162float(hb));
    }
}

// ---------------------------------------------------------------------------
extern "C" void kernel_launch(void* const* d_in, const int* in_sizes, int n_in,
                              void* d_out, int out_size) {
    const float* x  = (const float*)d_in[0];
    const float* Wq = (const float*)d_in[1];
    const float* Wk = (const float*)d_in[2];
    const float* Wv = (const float*)d_in[3];
    const float* Wo = (const float*)d_in[4];
    float* y = (float*)d_out;

    cudaFuncSetAttribute(gemm1_kernel,
                         cudaFuncAttributeMaxDynamicSharedMemorySize, GEMM_SMEM);
    cudaFuncSetAttribute(gemm2_kernel,
                         cudaFuncAttributeMaxDynamicSharedMemorySize, GEMM_SMEM);

    split_kernel<<<1280, 256>>>((const float4*)x, (const float4*)Wq,
                                (const float4*)Wk, (const float4*)Wv,
                                (const float4*)Wo);
    gemm1_kernel<<<dim3(24, 8), 256, GEMM_SMEM>>>();
    attn_kernel<<<512, 256>>>();
    gemm2_kernel<<<dim3(8, 8), 256, GEMM_SMEM>>>(y);
}

// round 8
// speedup vs baseline: 1.5929x; 1.0789x over previous
#include <cuda_runtime.h>
#include <cuda_bf16.h>
#include <math.h>
#include <stdint.h>

#define TT 512
#define DD 512
#define LOG2E 1.4426950408889634f

// ---------------------------------------------------------------------------
// Device-global scratch
// ---------------------------------------------------------------------------
__device__ float g_qkv[3 * DD * TT];                     // [w][o][t] fp32
__device__ __align__(16) __nv_bfloat16 g_aohi[DD * TT];  // ao hi, [d][t]
__device__ __align__(16) __nv_bfloat16 g_aolo[DD * TT];  // ao lo residual
__device__ __align__(16) __nv_bfloat16 gAhi[1536 * 512]; // Wq,Wk,Wv stacked hi
__device__ __align__(16) __nv_bfloat16 gAlo[1536 * 512];
__device__ __align__(16) __nv_bfloat16 gBhi[512 * 512];  // x [t][k]
__device__ __align__(16) __nv_bfloat16 gBlo[512 * 512];
__device__ __align__(16) __nv_bfloat16 gWohi[512 * 512]; // Wo [o][d]
__device__ __align__(16) __nv_bfloat16 gWolo[512 * 512];

__device__ __forceinline__ uint32_t smem_u32(const void* p) {
    uint32_t a;
    asm("{ .reg .u64 t; cvta.to.shared.u64 t, %1; cvt.u32.u64 %0, t; }"
        : "=r"(a) : "l"(p));
    return a;
}
__device__ __forceinline__ void cp16(uint32_t dst, const void* src) {
    asm volatile("cp.async.ca.shared.global [%0], [%1], 16;"
                 :: "r"(dst), "l"(src) : "memory");
}
__device__ __forceinline__ float fast_ex2(float x) {
    float r;
    asm("ex2.approx.ftz.f32 %0, %1;" : "=f"(r) : "f"(x));
    return r;
}

#define MMA16816(c, a, b) \
    asm volatile( \
        "mma.sync.aligned.m16n8k16.row.col.f32.bf16.bf16.f32 " \
        "{%0,%1,%2,%3},{%4,%5,%6,%7},{%8,%9},{%0,%1,%2,%3};" \
        : "+f"((c)[0]), "+f"((c)[1]), "+f"((c)[2]), "+f"((c)[3]) \
        : "r"((a)[0]), "r"((a)[1]), "r"((a)[2]), "r"((a)[3]), \
          "r"((b)[0]), "r"((b)[1]))

#define LDMX4(r, a) \
    asm volatile( \
        "ldmatrix.sync.aligned.m8n8.x4.shared.b16 {%0,%1,%2,%3}, [%4];" \
        : "=r"((r)[0]), "=r"((r)[1]), "=r"((r)[2]), "=r"((r)[3]) : "r"(a))

#define LDMX4T(r, a) \
    asm volatile( \
        "ldmatrix.sync.aligned.m8n8.x4.trans.shared.b16 {%0,%1,%2,%3}, [%4];" \
        : "=r"((r)[0]), "=r"((r)[1]), "=r"((r)[2]), "=r"((r)[3]) : "r"(a))

// ---------------------------------------------------------------------------
// Split kernel: fp32 -> bf16 hi + bf16 lo(residual).  (verified round 5)
// ---------------------------------------------------------------------------
__global__ void __launch_bounds__(256) split_kernel(
        const float4* __restrict__ x,  const float4* __restrict__ Wq,
        const float4* __restrict__ Wk, const float4* __restrict__ Wv,
        const float4* __restrict__ Wo) {
    const int gid = blockIdx.x * 256 + threadIdx.x;   // 0..327679
    const int seg = gid >> 16;
    const int off = gid & 65535;

    const float4* src;
    __nv_bfloat16 *dh, *dl;
    switch (seg) {
        case 0: src = Wq; dh = gAhi;          dl = gAlo;          break;
        case 1: src = Wk; dh = gAhi + 262144; dl = gAlo + 262144; break;
        case 2: src = Wv; dh = gAhi + 524288; dl = gAlo + 524288; break;
        case 3: src = x;  dh = gBhi;          dl = gBlo;          break;
        default: src = Wo; dh = gWohi;         dl = gWolo;         break;
    }
    float4 v = src[off];
    __nv_bfloat16 h0 = __float2bfloat16(v.x), h1 = __float2bfloat16(v.y);
    __nv_bfloat16 h2 = __float2bfloat16(v.z), h3 = __float2bfloat16(v.w);
    __nv_bfloat16 l0 = __float2bfloat16(v.x - __bfloat162float(h0));
    __nv_bfloat16 l1 = __float2bfloat16(v.y - __bfloat162float(h1));
    __nv_bfloat16 l2 = __float2bfloat16(v.z - __bfloat162float(h2));
    __nv_bfloat16 l3 = __float2bfloat16(v.w - __bfloat162float(h3));
    __nv_bfloat162* oh = (__nv_bfloat162*)dh;
    __nv_bfloat162* ol = (__nv_bfloat162*)dl;
    __nv_bfloat162 a, b;
    a.x = h0; a.y = h1; b.x = h2; b.y = h3;
    oh[off * 2] = a; oh[off * 2 + 1] = b;
    a.x = l0; a.y = l1; b.x = l2; b.y = l3;
    ol[off * 2] = a; ol[off * 2 + 1] = b;
}

// ---------------------------------------------------------------------------
// GEMM core: C[(m0+r)*512 + n0+c] = sum_k A[r][k]*B[c][k]
// CTA tile 32(m) x 64(n), 128 threads (4 warps, warp tile 16x32).
// ATRANS=false: A bf16 [m][k], ldmatrix non-trans, row stride 144B
// ATRANS=true : A bf16 [k][m], ldmatrix trans,     row stride 80B
// B: [n][k], row stride 144B. cp.async double-buffered, 3-pass hi/lo MMA.
// ---------------------------------------------------------------------------
#define B_MAT (64 * 144)             // 9216 B
#define GEMM_SMEM_MAX (2 * (2 * 5120 + 2 * B_MAT))   // 57344 B

template <bool ATRANS>
__device__ __forceinline__ void gemm_core(
        const uint4* __restrict__ AH, const uint4* __restrict__ AL,
        const uint4* __restrict__ BH, const uint4* __restrict__ BL,
        float* __restrict__ C) {
    extern __shared__ char smem[];
    const uint32_t s0 = smem_u32(smem);

    constexpr int AROWB = ATRANS ? 80 : 144;
    constexpr int A_MAT = ATRANS ? 64 * 80 : 32 * 144;
    constexpr int BUF = 2 * A_MAT + 2 * B_MAT;

    const int tid = threadIdx.x;       // 0..127
    const int wid = tid >> 5, lane = tid & 31;
    const int g = lane >> 2, t4 = lane & 3;
    const int wm = (wid & 1) * 16;     // warp m offset
    const int wn = (wid >> 1) * 32;    // warp n offset
    const int m0 = blockIdx.x * 32, n0 = blockIdx.y * 64;

    // ldmatrix lane addressing
    const int arow  = lane & 15;               // non-trans A row sel
    const int aksel = (lane >> 4) * 16;        // k-half byte offset
    const int brow  = ((lane >> 4) & 1) * 8 + (lane & 7);
    const int bksel = ((lane >> 3) & 1) * 16;
    const int laneRow  = ((lane >> 4) & 1) * 8 + (lane & 7);  // trans
    const int laneMsel = ((lane >> 3) & 1) * 8;

    float acc[4][4] = {};

    auto load_chunk = [&](int c, int b) {
        const uint32_t base = s0 + b * BUF;
        // A: 256 uint4 per matrix
#pragma unroll
        for (int it = 0; it < 2; it++) {
            const int idx = it * 128 + tid;
            size_t ga;
            uint32_t so;
            if (ATRANS) {
                const int row = idx >> 2, c16 = idx & 3;   // 64 k-rows x 4
                so = row * AROWB + c16 * 16;
                ga = (size_t)(c * 64 + row) * 64 + (m0 >> 3) + c16;
            } else {
                const int row = idx >> 3, c16 = idx & 7;   // 32 m-rows x 8
                so = row * AROWB + c16 * 16;
                ga = (size_t)(m0 + row) * 64 + c * 8 + c16;
            }
            cp16(base + so,         AH + ga);
            cp16(base + A_MAT + so, AL + ga);
        }
        // B: 512 uint4 per matrix
#pragma unroll
        for (int it = 0; it < 4; it++) {
            const int idx = it * 128 + tid;
            const int row = idx >> 3, c16 = idx & 7;
            const uint32_t so = row * 144 + c16 * 16;
            const size_t gb = (size_t)(n0 + row) * 64 + c * 8 + c16;
            cp16(base + 2 * A_MAT + so,         BH + gb);
            cp16(base + 2 * A_MAT + B_MAT + so, BL + gb);
        }
        asm volatile("cp.async.commit_group;" ::: "memory");
    };

    load_chunk(0, 0);

    for (int c = 0; c < 8; c++) {
        if (c < 7) {
            load_chunk(c + 1, (c + 1) & 1);
            asm volatile("cp.async.wait_group 1;" ::: "memory");
        } else {
            asm volatile("cp.async.wait_group 0;" ::: "memory");
        }
        __syncthreads();

        const uint32_t sb = s0 + (c & 1) * BUF;
#pragma unroll
        for (int ks = 0; ks < 4; ks++) {
            const int kO = ks * 32;
            uint32_t ah[4], al[4], bh[2][4], bl[2][4];
            if (ATRANS) {
                const uint32_t ad = sb + (ks * 16 + laneRow) * AROWB
                                  + (wm + laneMsel) * 2;
                LDMX4T(ah, ad);
                LDMX4T(al, ad + A_MAT);
            } else {
                const uint32_t ad = sb + (wm + arow) * AROWB + kO + aksel;
                LDMX4(ah, ad);
                LDMX4(al, ad + A_MAT);
            }
#pragma unroll
            for (int nb = 0; nb < 2; nb++) {
                const uint32_t bd = sb + 2 * A_MAT
                                  + (wn + nb * 16 + brow) * 144 + kO + bksel;
                LDMX4(bh[nb], bd);
                LDMX4(bl[nb], bd + B_MAT);
            }
#pragma unroll
            for (int nb = 0; nb < 2; nb++)
#pragma unroll
                for (int j = 0; j < 2; j++) {
                    MMA16816(acc[nb * 2 + j], ah, &bh[nb][j * 2]);
                    MMA16816(acc[nb * 2 + j], ah, &bl[nb][j * 2]);
                    MMA16816(acc[nb * 2 + j], al, &bh[nb][j * 2]);
                }
        }
        __syncthreads();
    }

    const int r = m0 + wm + g;
#pragma unroll
    for (int nb = 0; nb < 4; nb++) {
        const int col = n0 + wn + nb * 8 + 2 * t4;
        *(float2*)&C[(size_t)r * 512 + col] =
            make_float2(acc[nb][0], acc[nb][1]);
        *(float2*)&C[(size_t)(r + 8) * 512 + col] =
            make_float2(acc[nb][2], acc[nb][3]);
    }
}

__global__ void __launch_bounds__(128) gemm1_kernel() {
    gemm_core<false>((const uint4*)gAhi, (const uint4*)gAlo,
                     (const uint4*)gBhi, (const uint4*)gBlo, g_qkv);
}
__global__ void __launch_bounds__(128) gemm2_kernel(float* __restrict__ y) {
    gemm_core<true>((const uint4*)g_aohi, (const uint4*)g_aolo,
                    (const uint4*)gWohi, (const uint4*)gWolo, y);
}

// ---------------------------------------------------------------------------
// Attention with fused RoPE; writes bf16 hi/lo split directly ([d][t]).
// ---------------------------------------------------------------------------
__global__ void __launch_bounds__(256) attn_kernel() {
    const int c  = blockIdx.x;
    const int h  = c >> 6;
    const int ch = c & 63;
    const int fi = ch & 31;
    const int pc = ((h < 4) ? (h + 4) : (h - 4)) * 64 + ch;
    const float sgn = (h < 4) ? -1.0f : 1.0f;

    const float* q  = g_qkv + 0 * DD * TT + c  * TT;
    const float* qp = g_qkv + 0 * DD * TT + pc * TT;
    const float* k  = g_qkv + 1 * DD * TT + c  * TT;
    const float* kp = g_qkv + 1 * DD * TT + pc * TT;
    const float* v  = g_qkv + 2 * DD * TT + c  * TT;

    __shared__ float ks[512];
    __shared__ float vs[512];
    __shared__ float cs[512];
    __shared__ float sn[512];
    __shared__ float s_invf;

    const int tid = threadIdx.x;
    if (tid == 0) s_invf = (float)pow(10000.0, -(double)(2 * fi) / 64.0);
    __syncthreads();
    const float invf = s_invf;

#pragma unroll
    for (int off = 0; off < 512; off += 256) {
        const int tt = tid + off;
        float sv, cv;
        sincosf((float)tt * invf, &sv, &cv);
        cs[tt] = cv;
        sn[tt] = sv;
        ks[tt] = k[tt] * cv + sgn * kp[tt] * sv;
        vs[tt] = v[tt];
    }
    __syncthreads();

#pragma unroll
    for (int rep = 0; rep < 2; rep++) {
        const int i = rep ? (511 - tid) : tid;
        const float qr = q[i] * cs[i] + sgn * qp[i] * sn[i];
        const float qs = qr * (0.125f * LOG2E);
        float l = 0.f, acc = 0.f;
#pragma unroll 4
        for (int j = 0; j <= i; j++) {
            float p = fast_ex2(qs * ks[j]);
            l += p;
            acc += p * vs[j];
        }
        const float o = acc / l;
        const __nv_bfloat16 hb = __float2bfloat16(o);
        g_aohi[c * TT + i] = hb;
        g_aolo[c * TT + i] = __float2bfloat16(o - __bfloat162float(hb));
    }
}

// ---------------------------------------------------------------------------
extern "C" void kernel_launch(void* const* d_in, const int* in_sizes, int n_in,
                              void* d_out, int out_size) {
    const float* x  = (const float*)d_in[0];
    const float* Wq = (const float*)d_in[1];
    const float* Wk = (const float*)d_in[2];
    const float* Wv = (const float*)d_in[3];
    const float* Wo = (const float*)d_in[4];
    float* y = (float*)d_out;

    cudaFuncSetAttribute(gemm1_kernel,
                         cudaFuncAttributeMaxDynamicSharedMemorySize,
                         GEMM_SMEM_MAX);
    cudaFuncSetAttribute(gemm2_kernel,
                         cudaFuncAttributeMaxDynamicSharedMemorySize,
                         GEMM_SMEM_MAX);

    split_kernel<<<1280, 256>>>((const float4*)x, (const float4*)Wq,
                                (const float4*)Wk, (const float4*)Wv,
                                (const float4*)Wo);
    gemm1_kernel<<<dim3(48, 8), 128, GEMM_SMEM_MAX>>>();
    attn_kernel<<<512, 256>>>();
    gemm2_kernel<<<dim3(16, 8), 128, GEMM_SMEM_MAX>>>(y);
}